// round 12
// baseline (speedup 1.0000x reference)
#include <cuda_runtime.h>
#include <cuda_fp16.h>

// N=524288 residues, 21 residue types, 8 rigid frames, 24 atoms (12 atom-pairs).
static constexpr int BT = 192;   // threads per block
static constexpr int W  = 193;   // uint2-row stride for frames (193 ≡ 1 mod 32 -> conflict-free)

// Shared memory layout (word offsets)
static constexpr int S_TRANS2 = 0;                    // 48*21 float2, [pair][rt]
static constexpr int S_RIGP   = S_TRANS2 + 48*21*2;   // 12*3*21 float2: rig packed per atom-pair
static constexpr int S_RT     = S_RIGP   + 12*3*21*2; // BT ints
static constexpr int S_TDEPP  = S_RT     + BT;        // 2*21 u32 packed tdep bytes
static constexpr int S_RDPAIR = S_TDEPP  + 2*21;      // 12*21 u16 (rd0|rd1<<8) = 126 words
static constexpr int S_OPR2   = S_RDPAIR + 126;       // 24 rows * W uint2 (frames, 4 halves/uint2)
static constexpr int SMEM_WORDS = S_OPR2 + 24 * W * 2;
static constexpr int SMEM_BYTES = SMEM_WORDS * 4;     // 52,608 B -> 3 blocks/SM (RF allowing)

static_assert(S_OPR2 % 2 == 0, "uint2 region must be 8B aligned");

__global__ void __launch_bounds__(BT, 3)
backbone_kernel(const int* __restrict__ rtype,
                const float* __restrict__ bb,       // (N,4,3)
                const float* __restrict__ pos0,     // (N,3)
                const float* __restrict__ sc,       // (N,7,2)
                const float* __restrict__ g_trans,  // (21,8,4,3)
                const float* __restrict__ g_rig,    // (21,24,3)
                const int* __restrict__ g_tdep,     // (21,8)
                const int* __restrict__ g_rdep,     // (21,24)
                float* __restrict__ out, int nres)
{
    extern __shared__ float sm[];
    float2*         s_trans2 = (float2*)(sm + S_TRANS2);
    float2*         s_rigp   = (float2*)(sm + S_RIGP);
    int*            s_rt     = (int*)(sm + S_RT);
    unsigned*       s_tdepp  = (unsigned*)(sm + S_TDEPP);
    unsigned short* s_rdpair = (unsigned short*)(sm + S_RDPAIR);
    uint2*          s_opr2   = (uint2*)(sm + S_OPR2);  // index: (frame*3 + q)*W + tid

    const int tid  = threadIdx.x;
    const int lane = tid & 31;
    const int warp = tid >> 5;

    // ---- stage tables (stride-21 transposed -> conflict-free divergent-rt reads) ----
    {
        float* t2f = (float*)s_trans2;
        for (int i = tid; i < 96 * 21; i += BT) {
            const int rtt = i / 96, comp = i % 96;
            t2f[((comp >> 1) * 21 + rtt) * 2 + (comp & 1)] = g_trans[i];
        }
        // rig packed per atom-pair: flat comp = sub*3+j for atoms (2p, 2p+1)
        float* rpf = (float*)s_rigp;
        for (int i = tid; i < 72 * 21; i += BT) {
            const int rtt = i / 72, comp = i % 72;
            const int a = comp / 3, j = comp % 3;
            const int p = a >> 1, flat = (a & 1) * 3 + j;   // 0..5 within pair
            rpf[((p * 3 + (flat >> 1)) * 21 + rtt) * 2 + (flat & 1)] = g_rig[i];
        }
        for (int i = tid; i < 12 * 21; i += BT) {
            const int p = i % 12, rtt = i / 12;
            const unsigned r0 = (unsigned)g_rdep[rtt * 24 + 2*p]     & 0xFFu;
            const unsigned r1 = (unsigned)g_rdep[rtt * 24 + 2*p + 1] & 0xFFu;
            s_rdpair[p * 21 + rtt] = (unsigned short)(r0 | (r1 << 8));
        }
        for (int i = tid; i < 2 * 21; i += BT) {
            const int rtt = i >> 1, h = i & 1;
            unsigned wv = 0;
            #pragma unroll
            for (int b = 0; b < 4; b++)
                wv |= ((unsigned)g_tdep[rtt * 8 + h * 4 + b] & 0xFFu) << (8 * b);
            s_tdepp[i] = wv;
        }
    }
    __syncthreads();

    const int n  = blockIdx.x * BT + tid;
    const int nc = (n < nres) ? n : (nres - 1);   // clamp loads; stores gated later
    const int rt = rtype[nc];
    s_rt[tid] = rt;

    const unsigned dlo = s_tdepp[rt * 2 + 0];
    const unsigned dhi = s_tdepp[rt * 2 + 1];

    // ---- per-residue inputs (prefetched before the chain) ----
    const float4* bb4 = (const float4*)bb + (size_t)nc * 3;
    float4 b0 = bb4[0], b1 = bb4[1], b2 = bb4[2];
    const float2* sc2 = (const float2*)sc + (size_t)nc * 7;
    float2 cs[7];
    #pragma unroll
    for (int r = 0; r < 7; r++) cs[r] = sc2[r];

    const float Y00=b0.x, Y01=b0.y, Y02=b0.z;
    const float Y10=b0.w, Y11=b1.x, Y12=b1.y;
    const float Y20=b1.z, Y21=b1.w, Y22=b2.x;
    const float l0 = b2.y + pos0[nc*3+0];
    const float l1 = b2.z + pos0[nc*3+1];
    const float l2 = b2.w + pos0[nc*3+2];

    // ---- register-resident fp32 frames; sequential half2 pairing at store ----
    float f[8][12];

    #define STORE_FRAME(R) do {                                                   \
        __half2 h0 = __floats2half2_rn(f[R][0],  f[R][1]);                        \
        __half2 h1 = __floats2half2_rn(f[R][2],  f[R][3]);                        \
        __half2 h2 = __floats2half2_rn(f[R][4],  f[R][5]);                        \
        __half2 h3 = __floats2half2_rn(f[R][6],  f[R][7]);                        \
        __half2 h4 = __floats2half2_rn(f[R][8],  f[R][9]);                        \
        __half2 h5 = __floats2half2_rn(f[R][10], f[R][11]);                       \
        uint2 u0; u0.x = *(unsigned*)&h0; u0.y = *(unsigned*)&h1;                 \
        uint2 u1; u1.x = *(unsigned*)&h2; u1.y = *(unsigned*)&h3;                 \
        uint2 u2; u2.x = *(unsigned*)&h4; u2.y = *(unsigned*)&h5;                 \
        s_opr2[((R)*3 + 0)*W + tid] = u0;                                         \
        s_opr2[((R)*3 + 1)*W + tid] = u1;                                         \
        s_opr2[((R)*3 + 2)*W + tid] = u2;                                         \
    } while (0)

    // frame 0: combine(T[rt][0], opr0)
    {
        float X[12];
        #pragma unroll
        for (int cp = 0; cp < 6; cp++) {
            float2 x2 = s_trans2[cp * 21 + rt];
            X[2*cp] = x2.x; X[2*cp+1] = x2.y;
        }
        f[0][0] = X[0]*Y00 + X[1]*Y10 + X[2]*Y20;
        f[0][1] = X[0]*Y01 + X[1]*Y11 + X[2]*Y21;
        f[0][2] = X[0]*Y02 + X[1]*Y12 + X[2]*Y22;
        f[0][3] = X[3]*Y00 + X[4]*Y10 + X[5]*Y20;
        f[0][4] = X[3]*Y01 + X[4]*Y11 + X[5]*Y21;
        f[0][5] = X[3]*Y02 + X[4]*Y12 + X[5]*Y22;
        f[0][6] = X[6]*Y00 + X[7]*Y10 + X[8]*Y20;
        f[0][7] = X[6]*Y01 + X[7]*Y11 + X[8]*Y21;
        f[0][8] = X[6]*Y02 + X[7]*Y12 + X[8]*Y22;
        f[0][9]  = X[0]*l0 + X[1]*l1 + X[2]*l2 + X[9];
        f[0][10] = X[3]*l0 + X[4]*l1 + X[5]*l2 + X[10];
        f[0][11] = X[6]*l0 + X[7]*l1 + X[8]*l2 + X[11];
        STORE_FRAME(0);
    }

    // frames 1..7: SEL-selected prev (exact fp32), single fp16 rounding at store
    #pragma unroll
    for (int r = 1; r < 8; r++) {
        const float cc = cs[r-1].x, ss = cs[r-1].y;

        float Xr[12];
        #pragma unroll
        for (int cp = 0; cp < 6; cp++) {
            float2 x2 = s_trans2[(r*6 + cp) * 21 + rt];
            Xr[2*cp] = x2.x; Xr[2*cp+1] = x2.y;
        }

        // A = T[rt][r] composed with rot_x(c,s)   (translation unchanged)
        const float A0 = Xr[0], A1 = Xr[1]*cc + Xr[2]*ss, A2 = Xr[2]*cc - Xr[1]*ss;
        const float A3 = Xr[3], A4 = Xr[4]*cc + Xr[5]*ss, A5 = Xr[5]*cc - Xr[4]*ss;
        const float A6 = Xr[6], A7 = Xr[7]*cc + Xr[8]*ss, A8 = Xr[8]*cc - Xr[7]*ss;
        const float At0 = Xr[9], At1 = Xr[10], At2 = Xr[11];

        const int dep = (int)(((r < 4 ? dlo : dhi) >> ((r & 3) * 8)) & 0xFFu);

        float P[12];
        #pragma unroll
        for (int k = 0; k < 12; k++) P[k] = f[0][k];
        #pragma unroll
        for (int j = 1; j < 8; j++) {
            if (j < r) {                 // compile-time prune: dep < r
                const bool m = (dep == j);
                #pragma unroll
                for (int k = 0; k < 12; k++) P[k] = m ? f[j][k] : P[k];
            }
        }

        f[r][0] = P[0]*A0 + P[1]*A3 + P[2]*A6;
        f[r][1] = P[0]*A1 + P[1]*A4 + P[2]*A7;
        f[r][2] = P[0]*A2 + P[1]*A5 + P[2]*A8;
        f[r][3] = P[3]*A0 + P[4]*A3 + P[5]*A6;
        f[r][4] = P[3]*A1 + P[4]*A4 + P[5]*A7;
        f[r][5] = P[3]*A2 + P[4]*A5 + P[5]*A8;
        f[r][6] = P[6]*A0 + P[7]*A3 + P[8]*A6;
        f[r][7] = P[6]*A1 + P[7]*A4 + P[8]*A7;
        f[r][8] = P[6]*A2 + P[7]*A5 + P[8]*A8;
        f[r][9]  = P[0]*At0 + P[1]*At1 + P[2]*At2 + P[9];
        f[r][10] = P[3]*At0 + P[4]*At1 + P[5]*At2 + P[10];
        f[r][11] = P[6]*At0 + P[7]*At1 + P[8]*At2 + P[11];

        STORE_FRAME(r);
    }

    __syncwarp();   // atom phase reads frames of the whole warp (this warp produced them)

    // helper: transform one atom through a half2-packed frame
    #define ATOM_XFORM(U0, U1, U2, V0, V1, V2, O0, O1, O2) do {                   \
        float2 M01   = __half22float2(*(const __half2*)&(U0).x);                  \
        float2 M23   = __half22float2(*(const __half2*)&(U0).y);                  \
        float2 M45   = __half22float2(*(const __half2*)&(U1).x);                  \
        float2 M67   = __half22float2(*(const __half2*)&(U1).y);                  \
        float2 M89   = __half22float2(*(const __half2*)&(U2).x);                  \
        float2 M1011 = __half22float2(*(const __half2*)&(U2).y);                  \
        O0 = M01.x*(V0) + M01.y*(V1) + M23.x*(V2) + M89.y;                        \
        O1 = M23.y*(V0) + M45.x*(V1) + M45.y*(V2) + M1011.x;                      \
        O2 = M67.x*(V0) + M67.y*(V1) + M89.x*(V2) + M1011.y;                      \
    } while (0)

    // ---- warp-cooperative pair-task atom phase ----
    // task q = it*32+lane over (rho = q/12, pairIdx = q%12); atoms (2p, 2p+1).
    // Output addr = warpbase*72 + 6q -> 32 lanes span a contiguous 768B window.
    {
        const int wbase = warp * 32;
        const long resBase = (long)blockIdx.x * BT + wbase;
        float* owarp = out + resBase * 72;

        int rho = (lane < 12) ? 0 : ((lane < 24) ? 1 : 2);
        int p   = lane - rho * 12;

        #pragma unroll
        for (int it = 0; it < 12; ++it) {
            const int trho = wbase + rho;
            const int rtl  = s_rt[trho];
            const unsigned short rp = s_rdpair[p * 21 + rtl];
            const int rd0 = rp & 0xFF;
            const int rd1 = rp >> 8;

            uint2 a0 = s_opr2[(rd0*3 + 0)*W + trho];
            uint2 a1 = s_opr2[(rd0*3 + 1)*W + trho];
            uint2 a2 = s_opr2[(rd0*3 + 2)*W + trho];
            uint2 b0q = s_opr2[(rd1*3 + 0)*W + trho];
            uint2 b1q = s_opr2[(rd1*3 + 1)*W + trho];
            uint2 b2q = s_opr2[(rd1*3 + 2)*W + trho];

            const float2 g0 = s_rigp[(p*3 + 0) * 21 + rtl];  // (v0a, v1a)
            const float2 g1 = s_rigp[(p*3 + 1) * 21 + rtl];  // (v2a, v0b)
            const float2 g2 = s_rigp[(p*3 + 2) * 21 + rtl];  // (v1b, v2b)

            float o0, o1, o2, o3, o4, o5;
            ATOM_XFORM(a0,  a1,  a2,  g0.x, g0.y, g1.x, o0, o1, o2);
            ATOM_XFORM(b0q, b1q, b2q, g1.y, g2.x, g2.y, o3, o4, o5);

            if (resBase + rho < (long)nres) {
                float* pp = owarp + rho * 72 + p * 6;
                *(float2*)(pp + 0) = make_float2(o0, o1);
                *(float2*)(pp + 2) = make_float2(o2, o3);
                *(float2*)(pp + 4) = make_float2(o4, o5);
            }
            // advance q by 32: p += 8 (mod 12), rho takes the carry (+2, +1 on wrap)
            p += 8; rho += 2;
            if (p >= 12) { p -= 12; rho += 1; }
        }
    }

    // ---- second output: opr[:,0] (frame 0, sequential halves), coalesced ----
    {
        const int wbase = warp * 32;
        const long resBase = (long)blockIdx.x * BT + wbase;
        long rem = (long)nres - resBase;
        const int cnt = (rem >= 32) ? 32 : (rem > 0 ? (int)rem : 0);
        float* o2 = out + (long)nres * 72 + resBase * 12;
        const int tot = cnt * 12;
        for (int k = lane; k < tot; k += 32) {
            const int l = k / 12;
            const int c = k - l * 12;          // component 0..11 -> (q = c/4, half = c%4)
            const char* basep = (const char*)&s_opr2[(c >> 2)*W + wbase + l];
            const __half h = *(const __half*)(basep + (c & 3) * 2);
            o2[k] = __half2float(h);
        }
    }
}

extern "C" void kernel_launch(void* const* d_in, const int* in_sizes, int n_in,
                              void* d_out, int out_size)
{
    const int*   rtype   = (const int*)  d_in[0];
    const float* bb      = (const float*)d_in[1];
    const float* pos0    = (const float*)d_in[2];
    const float* sc      = (const float*)d_in[3];
    const float* g_trans = (const float*)d_in[4];
    const float* g_rig   = (const float*)d_in[5];
    const int*   g_tdep  = (const int*)  d_in[6];
    const int*   g_rdep  = (const int*)  d_in[7];
    float* out = (float*)d_out;

    const int nres = in_sizes[0];

    cudaFuncSetAttribute(backbone_kernel,
                         cudaFuncAttributeMaxDynamicSharedMemorySize, SMEM_BYTES);

    const int grid = (nres + BT - 1) / BT;
    backbone_kernel<<<grid, BT, SMEM_BYTES>>>(rtype, bb, pos0, sc,
                                              g_trans, g_rig, g_tdep, g_rdep,
                                              out, nres);
}

// round 13
// speedup vs baseline: 1.0509x; 1.0509x over previous
#include <cuda_runtime.h>
#include <cuda_fp16.h>

// N=524288 residues, 21 residue types, 8 rigid frames, 24 atoms (12 atom-pairs).
static constexpr int BT = 256;   // threads per block
static constexpr int W  = 257;   // uint2-row stride for frames (257 ≡ 1 mod 32 -> conflict-free)

// Shared memory layout (word offsets)
static constexpr int S_TRANS2 = 0;                    // 48*21 float2, [pair][rt]
static constexpr int S_RIGP   = S_TRANS2 + 48*21*2;   // 12*3*21 float2: rig packed per atom-pair
static constexpr int S_RT     = S_RIGP   + 12*3*21*2; // BT ints
static constexpr int S_TDEPP  = S_RT     + BT;        // 2*21 u32 packed tdep bytes
static constexpr int S_RDPAIR = S_TDEPP  + 2*21;      // 12*21 u16 (rd0|rd1<<8) = 126 words
static constexpr int S_OPR2   = S_RDPAIR + 126;       // 24 rows * W uint2 (frames, 4 halves/uint2)
static constexpr int SMEM_WORDS = S_OPR2 + 24 * W * 2;
static constexpr int SMEM_BYTES = SMEM_WORDS * 4;     // 65,408 B -> 2 blocks/SM (RF-bound anyway)

static_assert(S_OPR2 % 2 == 0, "uint2 region must be 8B aligned");

__global__ void __launch_bounds__(BT, 2)
backbone_kernel(const int* __restrict__ rtype,
                const float* __restrict__ bb,       // (N,4,3)
                const float* __restrict__ pos0,     // (N,3)
                const float* __restrict__ sc,       // (N,7,2)
                const float* __restrict__ g_trans,  // (21,8,4,3)
                const float* __restrict__ g_rig,    // (21,24,3)
                const int* __restrict__ g_tdep,     // (21,8)
                const int* __restrict__ g_rdep,     // (21,24)
                float* __restrict__ out, int nres)
{
    extern __shared__ float sm[];
    float2*         s_trans2 = (float2*)(sm + S_TRANS2);
    float2*         s_rigp   = (float2*)(sm + S_RIGP);
    int*            s_rt     = (int*)(sm + S_RT);
    unsigned*       s_tdepp  = (unsigned*)(sm + S_TDEPP);
    unsigned short* s_rdpair = (unsigned short*)(sm + S_RDPAIR);
    uint2*          s_opr2   = (uint2*)(sm + S_OPR2);  // index: (frame*3 + q)*W + tid

    const int tid  = threadIdx.x;
    const int lane = tid & 31;
    const int warp = tid >> 5;

    // ---- stage tables (stride-21 transposed -> conflict-free divergent-rt reads) ----
    {
        float* t2f = (float*)s_trans2;
        for (int i = tid; i < 96 * 21; i += BT) {
            const int rtt = i / 96, comp = i % 96;
            t2f[((comp >> 1) * 21 + rtt) * 2 + (comp & 1)] = g_trans[i];
        }
        // rig packed per atom-pair: flat comp = sub*3+j for atoms (2p, 2p+1)
        float* rpf = (float*)s_rigp;
        for (int i = tid; i < 72 * 21; i += BT) {
            const int rtt = i / 72, comp = i % 72;
            const int a = comp / 3, j = comp % 3;
            const int p = a >> 1, flat = (a & 1) * 3 + j;   // 0..5 within pair
            rpf[((p * 3 + (flat >> 1)) * 21 + rtt) * 2 + (flat & 1)] = g_rig[i];
        }
        for (int i = tid; i < 12 * 21; i += BT) {
            const int p = i % 12, rtt = i / 12;
            const unsigned r0 = (unsigned)g_rdep[rtt * 24 + 2*p]     & 0xFFu;
            const unsigned r1 = (unsigned)g_rdep[rtt * 24 + 2*p + 1] & 0xFFu;
            s_rdpair[p * 21 + rtt] = (unsigned short)(r0 | (r1 << 8));
        }
        for (int i = tid; i < 2 * 21; i += BT) {
            const int rtt = i >> 1, h = i & 1;
            unsigned wv = 0;
            #pragma unroll
            for (int b = 0; b < 4; b++)
                wv |= ((unsigned)g_tdep[rtt * 8 + h * 4 + b] & 0xFFu) << (8 * b);
            s_tdepp[i] = wv;
        }
    }
    __syncthreads();

    const int n  = blockIdx.x * BT + tid;
    const int nc = (n < nres) ? n : (nres - 1);   // clamp loads; stores gated later
    const int rt = rtype[nc];
    s_rt[tid] = rt;

    const unsigned dlo = s_tdepp[rt * 2 + 0];
    const unsigned dhi = s_tdepp[rt * 2 + 1];

    // ---- per-residue inputs (prefetched before the chain) ----
    const float4* bb4 = (const float4*)bb + (size_t)nc * 3;
    float4 b0 = bb4[0], b1 = bb4[1], b2 = bb4[2];
    const float2* sc2 = (const float2*)sc + (size_t)nc * 7;
    float2 cs[7];
    #pragma unroll
    for (int r = 0; r < 7; r++) cs[r] = sc2[r];

    const float Y00=b0.x, Y01=b0.y, Y02=b0.z;
    const float Y10=b0.w, Y11=b1.x, Y12=b1.y;
    const float Y20=b1.z, Y21=b1.w, Y22=b2.x;
    const float l0 = b2.y + pos0[nc*3+0];
    const float l1 = b2.z + pos0[nc*3+1];
    const float l2 = b2.w + pos0[nc*3+2];

    // ---- register-resident fp32 frames; sequential half2 pairing at store ----
    float f[8][12];

    #define STORE_FRAME(R) do {                                                   \
        __half2 h0 = __floats2half2_rn(f[R][0],  f[R][1]);                        \
        __half2 h1 = __floats2half2_rn(f[R][2],  f[R][3]);                        \
        __half2 h2 = __floats2half2_rn(f[R][4],  f[R][5]);                        \
        __half2 h3 = __floats2half2_rn(f[R][6],  f[R][7]);                        \
        __half2 h4 = __floats2half2_rn(f[R][8],  f[R][9]);                        \
        __half2 h5 = __floats2half2_rn(f[R][10], f[R][11]);                       \
        uint2 u0; u0.x = *(unsigned*)&h0; u0.y = *(unsigned*)&h1;                 \
        uint2 u1; u1.x = *(unsigned*)&h2; u1.y = *(unsigned*)&h3;                 \
        uint2 u2; u2.x = *(unsigned*)&h4; u2.y = *(unsigned*)&h5;                 \
        s_opr2[((R)*3 + 0)*W + tid] = u0;                                         \
        s_opr2[((R)*3 + 1)*W + tid] = u1;                                         \
        s_opr2[((R)*3 + 2)*W + tid] = u2;                                         \
    } while (0)

    // frame 0: combine(T[rt][0], opr0)
    {
        float X[12];
        #pragma unroll
        for (int cp = 0; cp < 6; cp++) {
            float2 x2 = s_trans2[cp * 21 + rt];
            X[2*cp] = x2.x; X[2*cp+1] = x2.y;
        }
        f[0][0] = X[0]*Y00 + X[1]*Y10 + X[2]*Y20;
        f[0][1] = X[0]*Y01 + X[1]*Y11 + X[2]*Y21;
        f[0][2] = X[0]*Y02 + X[1]*Y12 + X[2]*Y22;
        f[0][3] = X[3]*Y00 + X[4]*Y10 + X[5]*Y20;
        f[0][4] = X[3]*Y01 + X[4]*Y11 + X[5]*Y21;
        f[0][5] = X[3]*Y02 + X[4]*Y12 + X[5]*Y22;
        f[0][6] = X[6]*Y00 + X[7]*Y10 + X[8]*Y20;
        f[0][7] = X[6]*Y01 + X[7]*Y11 + X[8]*Y21;
        f[0][8] = X[6]*Y02 + X[7]*Y12 + X[8]*Y22;
        f[0][9]  = X[0]*l0 + X[1]*l1 + X[2]*l2 + X[9];
        f[0][10] = X[3]*l0 + X[4]*l1 + X[5]*l2 + X[10];
        f[0][11] = X[6]*l0 + X[7]*l1 + X[8]*l2 + X[11];
        STORE_FRAME(0);
    }

    // frames 1..7: SEL-selected prev (exact fp32), single fp16 rounding at store
    #pragma unroll
    for (int r = 1; r < 8; r++) {
        const float cc = cs[r-1].x, ss = cs[r-1].y;

        float Xr[12];
        #pragma unroll
        for (int cp = 0; cp < 6; cp++) {
            float2 x2 = s_trans2[(r*6 + cp) * 21 + rt];
            Xr[2*cp] = x2.x; Xr[2*cp+1] = x2.y;
        }

        // A = T[rt][r] composed with rot_x(c,s)   (translation unchanged)
        const float A0 = Xr[0], A1 = Xr[1]*cc + Xr[2]*ss, A2 = Xr[2]*cc - Xr[1]*ss;
        const float A3 = Xr[3], A4 = Xr[4]*cc + Xr[5]*ss, A5 = Xr[5]*cc - Xr[4]*ss;
        const float A6 = Xr[6], A7 = Xr[7]*cc + Xr[8]*ss, A8 = Xr[8]*cc - Xr[7]*ss;
        const float At0 = Xr[9], At1 = Xr[10], At2 = Xr[11];

        const int dep = (int)(((r < 4 ? dlo : dhi) >> ((r & 3) * 8)) & 0xFFu);

        float P[12];
        #pragma unroll
        for (int k = 0; k < 12; k++) P[k] = f[0][k];
        #pragma unroll
        for (int j = 1; j < 8; j++) {
            if (j < r) {                 // compile-time prune: dep < r
                const bool m = (dep == j);
                #pragma unroll
                for (int k = 0; k < 12; k++) P[k] = m ? f[j][k] : P[k];
            }
        }

        f[r][0] = P[0]*A0 + P[1]*A3 + P[2]*A6;
        f[r][1] = P[0]*A1 + P[1]*A4 + P[2]*A7;
        f[r][2] = P[0]*A2 + P[1]*A5 + P[2]*A8;
        f[r][3] = P[3]*A0 + P[4]*A3 + P[5]*A6;
        f[r][4] = P[3]*A1 + P[4]*A4 + P[5]*A7;
        f[r][5] = P[3]*A2 + P[4]*A5 + P[5]*A8;
        f[r][6] = P[6]*A0 + P[7]*A3 + P[8]*A6;
        f[r][7] = P[6]*A1 + P[7]*A4 + P[8]*A7;
        f[r][8] = P[6]*A2 + P[7]*A5 + P[8]*A8;
        f[r][9]  = P[0]*At0 + P[1]*At1 + P[2]*At2 + P[9];
        f[r][10] = P[3]*At0 + P[4]*At1 + P[5]*At2 + P[10];
        f[r][11] = P[6]*At0 + P[7]*At1 + P[8]*At2 + P[11];

        STORE_FRAME(r);
    }

    __syncwarp();   // atom phase reads frames of the whole warp (this warp produced them)

    // helper: transform one atom through a half2-packed frame
    #define ATOM_XFORM(U0, U1, U2, V0, V1, V2, O0, O1, O2) do {                   \
        float2 M01   = __half22float2(*(const __half2*)&(U0).x);                  \
        float2 M23   = __half22float2(*(const __half2*)&(U0).y);                  \
        float2 M45   = __half22float2(*(const __half2*)&(U1).x);                  \
        float2 M67   = __half22float2(*(const __half2*)&(U1).y);                  \
        float2 M89   = __half22float2(*(const __half2*)&(U2).x);                  \
        float2 M1011 = __half22float2(*(const __half2*)&(U2).y);                  \
        O0 = M01.x*(V0) + M01.y*(V1) + M23.x*(V2) + M89.y;                        \
        O1 = M23.y*(V0) + M45.x*(V1) + M45.y*(V2) + M1011.x;                      \
        O2 = M67.x*(V0) + M67.y*(V1) + M89.x*(V2) + M1011.y;                      \
    } while (0)

    // ---- warp-cooperative pair-task atom phase ----
    // task q = it*32+lane over (rho = q/12, pairIdx = q%12); atoms (2p, 2p+1).
    // Output addr = warpbase*72 + 6q -> 32 lanes span a contiguous 768B window.
    {
        const int wbase = warp * 32;
        const long resBase = (long)blockIdx.x * BT + wbase;
        float* owarp = out + resBase * 72;

        int rho = (lane < 12) ? 0 : ((lane < 24) ? 1 : 2);
        int p   = lane - rho * 12;

        #pragma unroll
        for (int it = 0; it < 12; ++it) {
            const int trho = wbase + rho;
            const int rtl  = s_rt[trho];
            const unsigned short rp = s_rdpair[p * 21 + rtl];
            const int rd0 = rp & 0xFF;
            const int rd1 = rp >> 8;

            uint2 a0 = s_opr2[(rd0*3 + 0)*W + trho];
            uint2 a1 = s_opr2[(rd0*3 + 1)*W + trho];
            uint2 a2 = s_opr2[(rd0*3 + 2)*W + trho];
            uint2 b0q = s_opr2[(rd1*3 + 0)*W + trho];
            uint2 b1q = s_opr2[(rd1*3 + 1)*W + trho];
            uint2 b2q = s_opr2[(rd1*3 + 2)*W + trho];

            const float2 g0 = s_rigp[(p*3 + 0) * 21 + rtl];  // (v0a, v1a)
            const float2 g1 = s_rigp[(p*3 + 1) * 21 + rtl];  // (v2a, v0b)
            const float2 g2 = s_rigp[(p*3 + 2) * 21 + rtl];  // (v1b, v2b)

            float o0, o1, o2, o3, o4, o5;
            ATOM_XFORM(a0,  a1,  a2,  g0.x, g0.y, g1.x, o0, o1, o2);
            ATOM_XFORM(b0q, b1q, b2q, g1.y, g2.x, g2.y, o3, o4, o5);

            if (resBase + rho < (long)nres) {
                float* pp = owarp + rho * 72 + p * 6;
                *(float2*)(pp + 0) = make_float2(o0, o1);
                *(float2*)(pp + 2) = make_float2(o2, o3);
                *(float2*)(pp + 4) = make_float2(o4, o5);
            }
            // advance q by 32: p += 8 (mod 12), rho takes the carry (+2, +1 on wrap)
            p += 8; rho += 2;
            if (p >= 12) { p -= 12; rho += 1; }
        }
    }

    // ---- second output: opr[:,0] (frame 0, sequential halves), coalesced ----
    {
        const int wbase = warp * 32;
        const long resBase = (long)blockIdx.x * BT + wbase;
        long rem = (long)nres - resBase;
        const int cnt = (rem >= 32) ? 32 : (rem > 0 ? (int)rem : 0);
        float* o2 = out + (long)nres * 72 + resBase * 12;
        const int tot = cnt * 12;
        for (int k = lane; k < tot; k += 32) {
            const int l = k / 12;
            const int c = k - l * 12;          // component 0..11 -> (q = c/4, half = c%4)
            const char* basep = (const char*)&s_opr2[(c >> 2)*W + wbase + l];
            const __half h = *(const __half*)(basep + (c & 3) * 2);
            o2[k] = __half2float(h);
        }
    }
}

extern "C" void kernel_launch(void* const* d_in, const int* in_sizes, int n_in,
                              void* d_out, int out_size)
{
    const int*   rtype   = (const int*)  d_in[0];
    const float* bb      = (const float*)d_in[1];
    const float* pos0    = (const float*)d_in[2];
    const float* sc      = (const float*)d_in[3];
    const float* g_trans = (const float*)d_in[4];
    const float* g_rig   = (const float*)d_in[5];
    const int*   g_tdep  = (const int*)  d_in[6];
    const int*   g_rdep  = (const int*)  d_in[7];
    float* out = (float*)d_out;

    const int nres = in_sizes[0];

    cudaFuncSetAttribute(backbone_kernel,
                         cudaFuncAttributeMaxDynamicSharedMemorySize, SMEM_BYTES);

    const int grid = (nres + BT - 1) / BT;
    backbone_kernel<<<grid, BT, SMEM_BYTES>>>(rtype, bb, pos0, sc,
                                              g_trans, g_rig, g_tdep, g_rdep,
                                              out, nres);
}